// round 5
// baseline (speedup 1.0000x reference)
#include <cuda_runtime.h>
#include <cuda_bf16.h>

// Output: [B=64, 4, 256, 256, 3] f32; scales sorted 32,64,128,256.
// Grid (64, 4, 64): each block handles 4 consecutive output rows of one
// (batch, scale) plane. 192 threads = one float4 column slot per row.
// Copy plane: 4 independent ld/st pairs per thread (MLP=4).
// Resize planes: x-interp weights hoisted (shared across the 4 rows),
// y-interp per row; pad groups are uniform (p, s multiples of 4).
// All output stores are streaming (__stcs) — output is never re-read.

#define HW    256
#define ROWF  (HW * 3)     // 768 floats per row
#define ROW4  (ROWF / 4)   // 192 float4 per row

__global__ void __launch_bounds__(192)
msp_kernel(const float* __restrict__ in, float4* __restrict__ out4)
{
    const int t     = threadIdx.x;      // 0..191
    const int ybase = blockIdx.x * 4;   // 0..252
    const int si    = blockIdx.y;       // 0..3
    const int b     = blockIdx.z;       // 0..63

    float4* __restrict__ dst = out4 + (((long long)(b * 4 + si) * HW + ybase) * ROW4) + t;

    if (si == 3) {
        // Native pass-through: 4 independent coalesced float4 copies.
        const float4* __restrict__ src =
            (const float4*)in + ((long long)b * HW + ybase) * ROW4 + t;
        float4 v0 = src[0 * ROW4];
        float4 v1 = src[1 * ROW4];
        float4 v2 = src[2 * ROW4];
        float4 v3 = src[3 * ROW4];
        __stcs(dst + 0 * ROW4, v0);
        __stcs(dst + 1 * ROW4, v1);
        __stcs(dst + 2 * ROW4, v2);
        __stcs(dst + 3 * ROW4, v3);
        return;
    }

    const int s = 32 << si;            // 32, 64, 128
    const int p = (HW - s) >> 1;       // centered pad (multiple of 4)

    if (ybase < p || ybase >= p + s) {
        // Uniform pad group: 4 zero stores.
        const float4 z = make_float4(0.f, 0.f, 0.f, 0.f);
        __stcs(dst + 0 * ROW4, z);
        __stcs(dst + 1 * ROW4, z);
        __stcs(dst + 2 * ROW4, z);
        __stcs(dst + 3 * ROW4, z);
        return;
    }

    // Interior group. Hoist x-direction data (identical for all 4 rows).
    const float r = 255.0f / (float)(s - 1);
    int   off0[4], off1[4];
    float wxk[4];
    bool  vld[4];
    const int f0 = t * 4;
    #pragma unroll
    for (int k = 0; k < 4; k++) {
        const int f = f0 + k;                    // float index in row, 0..767
        const int x = (int)((unsigned)f / 3u);   // pixel
        const int c = f - x * 3;                 // channel
        vld[k] = (x >= p) && (x < p + s);
        int xi = x - p;
        if (xi < 0) xi = 0;
        if (xi > s - 1) xi = s - 1;              // clamp so fx is always in range
        const float fx = (float)xi * r;
        int x0 = (int)fx; if (x0 > 255) x0 = 255;
        int x1 = min(x0 + 1, 255);
        off0[k] = x0 * 3 + c;
        off1[k] = x1 * 3 + c;
        wxk[k]  = fx - (float)x0;
    }

    #pragma unroll
    for (int q = 0; q < 4; q++) {
        const int y = ybase + q;
        const float fy = (float)(y - p) * r;
        int   y0 = (int)fy;       if (y0 > 255) y0 = 255;
        int   y1 = min(y0 + 1, 255);
        const float wy  = fy - (float)y0;
        const float omy = 1.0f - wy;

        const float* __restrict__ row0 = in + (b * HW + y0) * ROWF;
        const float* __restrict__ row1 = in + (b * HW + y1) * ROWF;

        float res[4];
        #pragma unroll
        for (int k = 0; k < 4; k++) {
            float val = 0.f;
            if (vld[k]) {
                const float wx  = wxk[k];
                const float omw = 1.0f - wx;
                const float top = __ldg(row0 + off0[k]) * omw + __ldg(row0 + off1[k]) * wx;
                const float bot = __ldg(row1 + off0[k]) * omw + __ldg(row1 + off1[k]) * wx;
                val = top * omy + bot * wy;
            }
            res[k] = val;
        }
        __stcs(dst + q * ROW4, make_float4(res[0], res[1], res[2], res[3]));
    }
}

extern "C" void kernel_launch(void* const* d_in, const int* in_sizes, int n_in,
                              void* d_out, int out_size)
{
    const float* images = (const float*)d_in[0];
    float4* out4 = (float4*)d_out;

    dim3 grid(HW / 4, 4, 64);   // 4-row groups, scale-index, batch
    dim3 block(192);
    msp_kernel<<<grid, block>>>(images, out4);
}